// round 7
// baseline (speedup 1.0000x reference)
#include <cuda_runtime.h>

#define T_TOTAL 34
#define H_OFF   4
#define TN      30     // output timesteps
#define NSTG    34     // staged timesteps (full row, trivial decode)
#define AP      128    // agents per ego group
#define NEGO    32
#define NTHR    1024   // 8 octants x 128 agents
#define TPQ     4      // timesteps per octant (octant 7 handles 2)
#define STRD    (AP + 1)   // padded smem stride (129 -> conflict-free)

// d^2 prefilter: boxes <= 2.0 per side -> corner radius <= sqrt(8).
// Overlap (loss > 0) impossible if center dist > 2*sqrt(8); margin included.
#define D2_THRESH 33.0f

__device__ __forceinline__ bool vm_at(const void* vm, int idx, int mode) {
    if (mode == 1) return ((const int*)vm)[idx] != 0;
    if (mode == 2) return ((const float*)vm)[idx] != 0.0f;
    return ((const unsigned char*)vm)[idx] != 0;
}

// max over 4 corners of min(long_t, lat_t) in frame at (px,py) rot (c,s).
__device__ __forceinline__ float corner_loss4(
    const float* cx, const float* cy, float px, float py,
    float c, float s, float bf, float br, float bl, float brt)
{
    float m = -1e30f;
    #pragma unroll
    for (int k = 0; k < 4; k++) {
        float dx = cx[k] - px, dy = cy[k] - py;
        float lx =  dx * c + dy * s;
        float ly = -dx * s + dy * c;
        float lt = fminf(fmaxf(bf  - lx, 0.0f), fmaxf(br  + lx, 0.0f));
        float la = fminf(fmaxf(bl  - ly, 0.0f), fmaxf(brt + ly, 0.0f));
        m = fmaxf(m, fminf(lt, la));
    }
    return m;
}

__global__ void __launch_bounds__(NTHR)
ttc_block(const float* __restrict__ posi,      // [N, 34, 2]
          const float* __restrict__ head,      // [N, 34]
          const float* __restrict__ box,       // [N, 4]  (f, r, l, rt)
          const void*  __restrict__ vm,        // [N, 34] bool (dtype detected)
          float* __restrict__ out)             // [32]
{
    const int b    = blockIdx.x;       // ego group
    const int e    = b * AP;           // ego agent index
    const int tid  = threadIdx.x;
    const int lane = tid & (AP - 1);   // agent within group
    const int q    = tid >> 7;         // octant 0..7
    const int n    = e + lane;
    const int tbeg = q * TPQ;          // 0,4,...,28

    // ---- valid-mask dtype detection (broadcast loads, uniform) ----
    const unsigned int* w = (const unsigned int*)vm;
    bool all01 = true, allf = true;
    #pragma unroll
    for (int i = 0; i < 8; i++) {
        unsigned int v = w[i];
        all01 = all01 && (v <= 1u);
        allf  = allf  && (v == 0u || v == 0x3F800000u);
    }
    const int mode = all01 ? 1 : (allf ? 2 : 0);

    // ---- coalesced staging: posi[e..e+128][0..34][2] -> transposed smem ----
    __shared__ float s_px[NSTG][STRD];
    __shared__ float s_py[NSTG][STRD];
    __shared__ float  s_ecx[TN][4], s_ecy[TN][4];
    __shared__ float4 s_epose[TN];     // (epx, epy, ce, se)
    __shared__ int    s_ev[TN];
    __shared__ float4 s_ebox;

    // block slab: 128 agents x 68 floats = 2176 float4 (16B-aligned)
    const float4* slab = (const float4*)(posi + (size_t)e * T_TOTAL * 2);
    #pragma unroll
    for (int k = tid; k < AP * (T_TOTAL / 2); k += NTHR) {   // <=3 iterations
        float4 v = slab[k];
        int a  = k / (T_TOTAL / 2);    // /17
        int kk = k - a * (T_TOTAL / 2);
        int t0 = 2 * kk;
        s_px[t0][a]     = v.x;  s_py[t0][a]     = v.y;
        s_px[t0 + 1][a] = v.z;  s_py[t0 + 1][a] = v.w;
    }

    // ---- ego staging: threads 0..29 build per-timestep ego pose/corners ----
    if (tid < TN) {
        const int ti  = tid + H_OFF;
        const int ebp = (e * T_TOTAL + ti) * 2;
        float2 ep0 = *(const float2*)(posi + ebp - 2);
        float2 ep1 = *(const float2*)(posi + ebp);
        float  eyaw = head[e * T_TOTAL + ti];
        float4 eb   = *(const float4*)(box + e * 4);
        s_ev[tid]   = vm_at(vm, e * T_TOTAL + ti, mode) ? 1 : 0;

        float epx = fmaf(ep1.x - ep0.x, 1.9f, ep1.x);
        float epy = fmaf(ep1.y - ep0.y, 1.9f, ep1.y);
        float ce = cosf(eyaw), se = sinf(eyaw);
        const float lxs[4] = { eb.x,  eb.x, -eb.y, -eb.y };
        const float lys[4] = { eb.z, -eb.w, -eb.w,  eb.z };
        #pragma unroll
        for (int k = 0; k < 4; k++) {
            s_ecx[tid][k] = lxs[k] * ce - lys[k] * se + epx;
            s_ecy[tid][k] = lxs[k] * se + lys[k] * ce + epy;
        }
        s_epose[tid] = make_float4(epx, epy, ce, se);
        if (tid == 0) s_ebox = eb;
    }
    __syncthreads();

    bool viol = false;
    if (lane != 0) {                   // lane 0 is the ego itself (excluded edge)
        #pragma unroll
        for (int i = 0; i < TPQ; i++) {
            const int t = tbeg + i;    // output timestep
            if (t >= TN) break;        // uniform (octant 7 only)
            const int ti = t + H_OFF;

            // agent extrapolated center from staged positions (conflict-free LDS)
            float p0x = s_px[ti - 1][lane], p0y = s_py[ti - 1][lane];
            float p1x = s_px[ti][lane],     p1y = s_py[ti][lane];
            float apx = fmaf(p1x - p0x, 1.9f, p1x);
            float apy = fmaf(p1y - p0y, 1.9f, p1y);

            float4 ep = s_epose[t];
            float ddx = apx - ep.x, ddy = apy - ep.y;
            float d2 = fmaf(ddx, ddx, ddy * ddy);
            if (d2 > D2_THRESH) continue;              // cheap reject (~99%)
            if (!s_ev[t]) continue;
            if (!vm_at(vm, n * T_TOTAL + ti, mode)) continue;

            // ---- rare full evaluation ----
            float ayaw = head[n * T_TOTAL + ti];
            float4 ab  = *(const float4*)(box + n * 4);
            float ca = cosf(ayaw), sa = sinf(ayaw);

            // L1: ego corners in agent frame / agent box
            float ecx[4], ecy[4];
            #pragma unroll
            for (int k = 0; k < 4; k++) { ecx[k] = s_ecx[t][k]; ecy[k] = s_ecy[t][k]; }
            float L1 = corner_loss4(ecx, ecy, apx, apy, ca, sa,
                                    ab.x, ab.y, ab.z, ab.w);

            // agent corners (world)
            float acx[4], acy[4];
            const float lxs[4] = { ab.x,  ab.x, -ab.y, -ab.y };
            const float lys[4] = { ab.z, -ab.w, -ab.w,  ab.z };
            #pragma unroll
            for (int k = 0; k < 4; k++) {
                acx[k] = lxs[k] * ca - lys[k] * sa + apx;
                acy[k] = lxs[k] * sa + lys[k] * ca + apy;
            }
            // L2: agent corners in ego frame / ego box
            float4 eb = s_ebox;
            float L2 = corner_loss4(acx, acy, ep.x, ep.y, ep.z, ep.w,
                                    eb.x, eb.y, eb.z, eb.w);

            viol = viol || (fmaxf(L1, L2) > 0.0f);
        }
    }

    int any = __syncthreads_or(viol ? 1 : 0);
    if (tid == 0) out[b] = any ? 0.0f : 1.0f;
}

extern "C" void kernel_launch(void* const* d_in, const int* in_sizes, int n_in,
                              void* d_out, int out_size) {
    const float* posi = (const float*)d_in[0];   // infer_position
    const float* head = (const float*)d_in[1];   // infer_heading
    const float* box  = (const float*)d_in[2];   // box
    const void*  vm   = (const void*)d_in[3];    // infer_valid_mask
    float* out = (float*)d_out;

    ttc_block<<<NEGO, NTHR>>>(posi, head, box, vm, out);
}

// round 8
// speedup vs baseline: 1.0258x; 1.0258x over previous
#include <cuda_runtime.h>

#define T_TOTAL 34
#define H_OFF   4
#define TN      30     // output timesteps
#define AP      128    // agents per ego group
#define NEGO    32
#define NTHR    1024   // 8 octants x 128 agents
#define TPQ     4      // timesteps per octant (octant 7 handles 2)
#define STRD    (AP + 1)   // padded float stride -> conflict-free LDS

// d^2 prefilter: boxes <= 2.0 per side -> corner radius <= sqrt(8).
// Overlap (loss > 0) impossible if center dist > 2*sqrt(8); margin included.
#define D2_THRESH 33.0f

struct Smem {
    float         px[T_TOTAL][STRD];
    float         py[T_TOTAL][STRD];
    float         hd[T_TOTAL][STRD];
    unsigned char vmb[T_TOTAL][132];   // decoded valid mask; lane 0 = ego
    float         ecx[TN][4], ecy[TN][4];
    float4        epose[TN];           // (epx, epy, ce, se)
    float4        ebox;
    float4        abox[AP];
};

// max over 4 corners of min(long_t, lat_t) in frame at (px,py) rot (c,s).
__device__ __forceinline__ float corner_loss4(
    const float* cx, const float* cy, float px, float py,
    float c, float s, float bf, float br, float bl, float brt)
{
    float m = -1e30f;
    #pragma unroll
    for (int k = 0; k < 4; k++) {
        float dx = cx[k] - px, dy = cy[k] - py;
        float lx =  dx * c + dy * s;
        float ly = -dx * s + dy * c;
        float lt = fminf(fmaxf(bf  - lx, 0.0f), fmaxf(br  + lx, 0.0f));
        float la = fminf(fmaxf(bl  - ly, 0.0f), fmaxf(brt + ly, 0.0f));
        m = fmaxf(m, fminf(lt, la));
    }
    return m;
}

__global__ void __launch_bounds__(NTHR)
ttc_block(const float* __restrict__ posi,      // [N, 34, 2]
          const float* __restrict__ head,      // [N, 34]
          const float* __restrict__ box,       // [N, 4]  (f, r, l, rt)
          const void*  __restrict__ vm,        // [N, 34] bool (dtype detected)
          float* __restrict__ out)             // [32]
{
    extern __shared__ char smem_raw[];
    Smem* S = (Smem*)smem_raw;

    const int b    = blockIdx.x;       // ego group
    const int e    = b * AP;           // ego agent index (== lane 0)
    const int tid  = threadIdx.x;
    const int lane = tid & (AP - 1);
    const int q    = tid >> 7;         // octant 0..7
    const int tbeg = q * TPQ;

    // ---- valid-mask dtype detection (broadcast loads, issued first) ----
    const unsigned int* w = (const unsigned int*)vm;
    bool wordmode = true;              // int32 or float32 bool: entry = word != 0
    #pragma unroll
    for (int i = 0; i < 8; i++) {
        unsigned int v = w[i];
        wordmode = wordmode && (v <= 1u || v == 0x3F800000u);
    }

    // ---- position slab: 2176 float4, coalesced -> transposed smem ----
    const float4* pslab = (const float4*)(posi + (size_t)e * T_TOTAL * 2);
    #pragma unroll
    for (int k = tid; k < AP * (T_TOTAL / 2); k += NTHR) {
        float4 v = pslab[k];
        int a  = k / (T_TOTAL / 2);
        int t0 = 2 * (k - a * (T_TOTAL / 2));
        S->px[t0][a]     = v.x;  S->py[t0][a]     = v.y;
        S->px[t0 + 1][a] = v.z;  S->py[t0 + 1][a] = v.w;
    }

    // ---- heading slab: 1088 float4, coalesced -> transposed smem ----
    const float4* hslab = (const float4*)(head + (size_t)e * T_TOTAL);
    #pragma unroll
    for (int k = tid; k < AP * T_TOTAL / 4; k += NTHR) {
        float4 v = hslab[k];
        int idx = 4 * k;
        int a = idx / T_TOTAL, tt = idx - a * T_TOTAL;
        float vv[4] = { v.x, v.y, v.z, v.w };
        #pragma unroll
        for (int j = 0; j < 4; j++) {
            S->hd[tt][a] = vv[j];
            if (++tt == T_TOTAL) { tt = 0; ++a; }
        }
    }

    // ---- box slab: 128 float4, coalesced ----
    if (tid < AP) S->abox[tid] = *(const float4*)(box + (size_t)(e + tid) * 4);

    // ---- valid-mask slab: decode to bytes (depends on mode -> 2nd trip) ----
    if (wordmode) {
        const uint4* vs = (const uint4*)((const unsigned int*)vm + (size_t)e * T_TOTAL);
        #pragma unroll
        for (int k = tid; k < AP * T_TOTAL / 4; k += NTHR) {   // 1088
            uint4 u = vs[k];
            int idx = 4 * k;
            int a = idx / T_TOTAL, tt = idx - a * T_TOTAL;
            unsigned int uu[4] = { u.x, u.y, u.z, u.w };
            #pragma unroll
            for (int j = 0; j < 4; j++) {
                S->vmb[tt][a] = (uu[j] != 0u);
                if (++tt == T_TOTAL) { tt = 0; ++a; }
            }
        }
    } else {
        const uint4* vs = (const uint4*)((const unsigned char*)vm + (size_t)e * T_TOTAL);
        for (int k = tid; k < AP * T_TOTAL / 16; k += NTHR) {  // 272
            uint4 u = vs[k];
            unsigned int uu[4] = { u.x, u.y, u.z, u.w };
            int idx = 16 * k;
            int a = idx / T_TOTAL, tt = idx - a * T_TOTAL;
            #pragma unroll
            for (int wj = 0; wj < 4; wj++)
                #pragma unroll
                for (int bj = 0; bj < 4; bj++) {
                    S->vmb[tt][a] = ((uu[wj] >> (8 * bj)) & 0xFFu) != 0u;
                    if (++tt == T_TOTAL) { tt = 0; ++a; }
                }
        }
    }

    // ---- ego staging: threads 0..29 build per-timestep ego pose/corners ----
    if (tid < TN) {
        const int ti  = tid + H_OFF;
        const int ebp = (e * T_TOTAL + ti) * 2;
        float2 ep0 = *(const float2*)(posi + ebp - 2);
        float2 ep1 = *(const float2*)(posi + ebp);
        float  eyaw = head[e * T_TOTAL + ti];
        float4 eb   = *(const float4*)(box + (size_t)e * 4);

        float epx = fmaf(ep1.x - ep0.x, 1.9f, ep1.x);
        float epy = fmaf(ep1.y - ep0.y, 1.9f, ep1.y);
        float ce = cosf(eyaw), se = sinf(eyaw);
        const float lxs[4] = { eb.x,  eb.x, -eb.y, -eb.y };
        const float lys[4] = { eb.z, -eb.w, -eb.w,  eb.z };
        #pragma unroll
        for (int k = 0; k < 4; k++) {
            S->ecx[tid][k] = lxs[k] * ce - lys[k] * se + epx;
            S->ecy[tid][k] = lxs[k] * se + lys[k] * ce + epy;
        }
        S->epose[tid] = make_float4(epx, epy, ce, se);
        if (tid == 0) S->ebox = eb;
    }
    __syncthreads();

    // ---- post-barrier: pure SMEM/ALU, no DRAM ----
    bool viol = false;
    if (lane != 0) {                   // lane 0 is the ego itself (excluded edge)
        #pragma unroll
        for (int i = 0; i < TPQ; i++) {
            const int t = tbeg + i;
            if (t >= TN) break;        // uniform (octant 7 only)
            const int ti = t + H_OFF;

            float p0x = S->px[ti - 1][lane], p0y = S->py[ti - 1][lane];
            float p1x = S->px[ti][lane],     p1y = S->py[ti][lane];
            float apx = fmaf(p1x - p0x, 1.9f, p1x);
            float apy = fmaf(p1y - p0y, 1.9f, p1y);

            float4 ep = S->epose[t];
            float ddx = apx - ep.x, ddy = apy - ep.y;
            float d2 = fmaf(ddx, ddx, ddy * ddy);

            bool ok = (d2 <= D2_THRESH) && S->vmb[ti][lane] && S->vmb[ti][0];
            if (!ok) continue;

            // ---- rare full evaluation (all operands in SMEM/regs) ----
            float ayaw = S->hd[ti][lane];
            float4 ab  = S->abox[lane];
            float ca = cosf(ayaw), sa = sinf(ayaw);

            float ecx[4], ecy[4];
            #pragma unroll
            for (int k = 0; k < 4; k++) { ecx[k] = S->ecx[t][k]; ecy[k] = S->ecy[t][k]; }
            float L1 = corner_loss4(ecx, ecy, apx, apy, ca, sa,
                                    ab.x, ab.y, ab.z, ab.w);

            float acx[4], acy[4];
            const float lxs[4] = { ab.x,  ab.x, -ab.y, -ab.y };
            const float lys[4] = { ab.z, -ab.w, -ab.w,  ab.z };
            #pragma unroll
            for (int k = 0; k < 4; k++) {
                acx[k] = lxs[k] * ca - lys[k] * sa + apx;
                acy[k] = lxs[k] * sa + lys[k] * ca + apy;
            }
            float4 eb = S->ebox;
            float L2 = corner_loss4(acx, acy, ep.x, ep.y, ep.z, ep.w,
                                    eb.x, eb.y, eb.z, eb.w);

            viol = viol || (fmaxf(L1, L2) > 0.0f);
        }
    }

    int any = __syncthreads_or(viol ? 1 : 0);
    if (tid == 0) out[b] = any ? 0.0f : 1.0f;
}

extern "C" void kernel_launch(void* const* d_in, const int* in_sizes, int n_in,
                              void* d_out, int out_size) {
    const float* posi = (const float*)d_in[0];   // infer_position
    const float* head = (const float*)d_in[1];   // infer_heading
    const float* box  = (const float*)d_in[2];   // box
    const void*  vm   = (const void*)d_in[3];    // infer_valid_mask
    float* out = (float*)d_out;

    static bool attr_set = false;
    if (!attr_set) {
        cudaFuncSetAttribute(ttc_block, cudaFuncAttributeMaxDynamicSharedMemorySize,
                             (int)sizeof(Smem));
        attr_set = true;
    }
    ttc_block<<<NEGO, NTHR, sizeof(Smem)>>>(posi, head, box, vm, out);
}